// round 13
// baseline (speedup 1.0000x reference)
#include <cuda_runtime.h>
#include <cuda_bf16.h>
#include <cstdint>
#include <math.h>

// Problem dims
#define VV 16000
#define BB 32
#define TT 256
#define EE 512
#define GE 2048          // 4*E
#define MROWS 8192       // B*T
#define NPADV 16128      // 126*128, padded vocab for GEMM tiles
#define NXB 125          // real 128-col blocks in vocab (125*128 = 16000)

#define LNBLK 64         // LSTM persistent blocks
#define NTHR 256

// ---------------- scratch (device globals; no allocation allowed) -------------
__device__ __align__(16) float g_G   [(size_t)MROWS * GE];     // x@Wx+b (reused per layer)
__device__ __align__(16) __nv_bfloat16 g_HpHi[2 * BB * EE];    // h ping-pong hi
__device__ __align__(16) __nv_bfloat16 g_HpLo[2 * BB * EE];    // h ping-pong lo
__device__ __align__(16) __nv_bfloat16 g_Ahi[(size_t)MROWS * EE];   // A operand hi
__device__ __align__(16) __nv_bfloat16 g_Alo[(size_t)MROWS * EE];   // A operand lo
__device__ __align__(16) __nv_bfloat16 g_WThi[(size_t)NPADV * EE];  // W^T hi [Npad][512]
__device__ __align__(16) __nv_bfloat16 g_WTlo[(size_t)NPADV * EE];  // W^T lo
__device__ __align__(16) __nv_bfloat16 g_Wh0Thi[(size_t)GE * EE];   // Wh0^T hi
__device__ __align__(16) __nv_bfloat16 g_Wh0Tlo[(size_t)GE * EE];
__device__ __align__(16) __nv_bfloat16 g_Wh1Thi[(size_t)GE * EE];   // Wh1^T hi
__device__ __align__(16) __nv_bfloat16 g_Wh1Tlo[(size_t)GE * EE];
__device__ float g_pm [(size_t)MROWS * NXB];   // per-(row, xblock) softmax max
__device__ float g_ps [(size_t)MROWS * NXB];   // per-(row, xblock) softmax sum
__device__ float g_nll [MROWS];
__device__ unsigned g_bar_cnt;
__device__ unsigned g_bar_gen;

// ---------------- helpers ----------------
__device__ __forceinline__ float sigm(float x) { return 1.0f / (1.0f + expf(-x)); }

__device__ __forceinline__ unsigned ld_acq(const unsigned* p) {
    unsigned v;
    asm volatile("ld.acquire.gpu.u32 %0, [%1];" : "=r"(v) : "l"(p) : "memory");
    return v;
}

__device__ __forceinline__ void cp_async16(unsigned int dst, const void* src) {
    asm volatile("cp.async.cg.shared.global [%0], [%1], 16;" :: "r"(dst), "l"(src));
}
__device__ __forceinline__ void cp_commit() { asm volatile("cp.async.commit_group;"); }
template<int N> __device__ __forceinline__ void cp_wait() {
    asm volatile("cp.async.wait_group %0;" :: "n"(N));
}

__device__ __forceinline__ void grid_barrier(unsigned& mygen) {
    __syncthreads();
    if (threadIdx.x == 0) {
        unsigned a = atomicAdd(&g_bar_cnt, 1u);
        if (a == LNBLK - 1) {
            g_bar_cnt = 0u;
            __threadfence();
            atomicAdd(&g_bar_gen, 1u);
        } else {
            while (ld_acq(&g_bar_gen) == mygen) { }
        }
        mygen++;
    }
    __syncthreads();
}

// ---------------- mma.sync helpers (compute_80 PTX — HMMA on sm_103) ----------
__device__ __forceinline__ void ldsm4(unsigned& r0, unsigned& r1, unsigned& r2,
                                      unsigned& r3, unsigned addr) {
    asm volatile("ldmatrix.sync.aligned.m8n8.x4.shared.b16 {%0,%1,%2,%3}, [%4];"
                 : "=r"(r0), "=r"(r1), "=r"(r2), "=r"(r3) : "r"(addr));
}
__device__ __forceinline__ void mma16816(float* d, const unsigned* a, const unsigned* b) {
    asm volatile(
        "mma.sync.aligned.m16n8k16.row.col.f32.bf16.bf16.f32 "
        "{%0,%1,%2,%3}, {%4,%5,%6,%7}, {%8,%9}, {%0,%1,%2,%3};"
        : "+f"(d[0]), "+f"(d[1]), "+f"(d[2]), "+f"(d[3])
        : "r"(a[0]), "r"(a[1]), "r"(a[2]), "r"(a[3]), "r"(b[0]), "r"(b[1]));
}

// ---------------- init: reset barrier state ----------------
__global__ void init_kernel() {
    if (threadIdx.x == 0) { g_bar_cnt = 0u; g_bar_gen = 0u; }
}

// ---------------- embedding gather -> split bf16 A operand ----------------
__global__ void embed_kernel(const int* __restrict__ inputs, const float* __restrict__ Emat) {
    int idx = blockIdx.x * blockDim.x + threadIdx.x;
    if (idx >= MROWS * (EE / 4)) return;
    int r  = idx >> 7;
    int e4 = idx & 127;
    int t = r >> 5;
    int b = r & 31;
    int tok = inputs[b * TT + t];
    float4 v = reinterpret_cast<const float4*>(Emat)[(size_t)tok * 128 + e4];
    size_t base = (size_t)r * EE + e4 * 4;
    __nv_bfloat162 h01 = __floats2bfloat162_rn(v.x, v.y);
    __nv_bfloat162 h23 = __floats2bfloat162_rn(v.z, v.w);
    *reinterpret_cast<__nv_bfloat162*>(&g_Ahi[base])     = h01;
    *reinterpret_cast<__nv_bfloat162*>(&g_Ahi[base + 2]) = h23;
    __nv_bfloat162 l01 = __floats2bfloat162_rn(v.x - __bfloat162float(h01.x),
                                               v.y - __bfloat162float(h01.y));
    __nv_bfloat162 l23 = __floats2bfloat162_rn(v.z - __bfloat162float(h23.x),
                                               v.w - __bfloat162float(h23.y));
    *reinterpret_cast<__nv_bfloat162*>(&g_Alo[base])     = l01;
    *reinterpret_cast<__nv_bfloat162*>(&g_Alo[base + 2]) = l23;
}

// ---------------- weight transpose + bf16 split: W[512][N] -> dst[N][512] -----
__global__ void transpose_split_kernel(const float* __restrict__ W, int N,
                                       __nv_bfloat16* __restrict__ dsthi,
                                       __nv_bfloat16* __restrict__ dstlo) {
    __shared__ float tile[32][33];
    int bx = blockIdx.x * 32;
    int by = blockIdx.y * 32;
    int tx = threadIdx.x;
    int ty = threadIdx.y;
    #pragma unroll
    for (int j = 0; j < 4; j++) {
        int k = by + ty + j * 8;
        int n = bx + tx;
        tile[ty + j * 8][tx] = (n < N) ? W[(size_t)k * N + n] : 0.0f;
    }
    __syncthreads();
    #pragma unroll
    for (int j = 0; j < 4; j++) {
        int n = bx + ty + j * 8;
        int k = by + tx;
        float v = tile[tx][ty + j * 8];
        __nv_bfloat16 h = __float2bfloat16(v);
        dsthi[(size_t)n * EE + k] = h;
        dstlo[(size_t)n * EE + k] = __float2bfloat16(v - __bfloat162float(h));
    }
}

// ---------------- bf16 mma GEMM (Round-9 config) + optional fused softmax -----
#define LDT 72
#define ROWB (LDT * 2)                    // 144
#define TILEA_BYTES (128 * ROWB)          // 18432
#define STAGE_BYTES (2 * TILEA_BYTES)     // 36864
#define NSTAGE 3
#define GEMM_SMEM (NSTAGE * STAGE_BYTES)  // 110592

__global__ __launch_bounds__(256, 2)
void gemm_mma(const __nv_bfloat16* __restrict__ Ahi, const __nv_bfloat16* __restrict__ Alo,
              const float* __restrict__ bias, float* __restrict__ C, int N_real,
              int do_sm)
{
    extern __shared__ __align__(16) char smem[];
    __shared__ float sbias[128];

    int tid = threadIdx.x;
    int wid = tid >> 5;
    int lane = tid & 31;
    int wm = wid & 1;
    int wn = wid >> 1;
    int n0 = blockIdx.x * 128;
    int m0 = blockIdx.y * 128;

    unsigned sbase = (unsigned)__cvta_generic_to_shared(smem);

    for (int i = tid; i < 128; i += 256) {
        int n = n0 + i;
        sbias[i] = (n < N_real) ? bias[n] : 0.0f;
    }

    int g  = lane >> 3;
    int lr = lane & 7;
    unsigned aoff[4];
    #pragma unroll
    for (int mi = 0; mi < 4; mi++)
        aoff[mi] = (unsigned)((wm * 64 + mi * 16 + (g & 1) * 8 + lr) * ROWB
                              + (g >> 1) * 16);
    unsigned boff[2];
    #pragma unroll
    for (int ni2 = 0; ni2 < 2; ni2++)
        boff[ni2] = (unsigned)(TILEA_BYTES + (wn * 32 + ni2 * 16 + (g >> 1) * 8 + lr) * ROWB
                               + (g & 1) * 16);

    float acc[4][4][4];
    #pragma unroll
    for (int i = 0; i < 4; i++)
        #pragma unroll
        for (int j = 0; j < 4; j++)
            #pragma unroll
            for (int r = 0; r < 4; r++) acc[i][j][r] = 0.0f;

    const int NCH = 24;

    auto load_chunk = [&](int c, int stage) {
        int phase = c >> 3;
        int k0 = (c & 7) * 64;
        const __nv_bfloat16* Asrc = (phase == 1) ? Alo : Ahi;
        const __nv_bfloat16* Bsrc = (phase == 2) ? g_WTlo : g_WThi;
        unsigned dstA = sbase + stage * STAGE_BYTES;
        unsigned dstB = dstA + TILEA_BYTES;
        #pragma unroll
        for (int q = 0; q < 8; q++) {
            int idx = tid + q * 256;
            if (idx < 1024) {
                int row = idx >> 3, gg = idx & 7;
                cp_async16(dstA + row * ROWB + gg * 16,
                           Asrc + (size_t)(m0 + row) * EE + k0 + gg * 8);
            } else {
                int idx2 = idx - 1024;
                int row = idx2 >> 3, gg = idx2 & 7;
                cp_async16(dstB + row * ROWB + gg * 16,
                           Bsrc + (size_t)(n0 + row) * EE + k0 + gg * 8);
            }
        }
        cp_commit();
    };

    load_chunk(0, 0);
    load_chunk(1, 1);

    int stage = 0;
    #pragma unroll 1
    for (int c = 0; c < NCH; c++) {
        if (c + 2 < NCH) cp_wait<1>(); else cp_wait<0>();
        __syncthreads();
        if (c + 2 < NCH)
            load_chunk(c + 2, (c + 2) % NSTAGE);

        unsigned sb = sbase + stage * STAGE_BYTES;
        #pragma unroll
        for (int ks = 0; ks < 4; ks++) {
            unsigned a[4][4], b[4][2];
            #pragma unroll
            for (int mi = 0; mi < 4; mi++)
                ldsm4(a[mi][0], a[mi][1], a[mi][2], a[mi][3],
                      sb + aoff[mi] + ks * 32);
            #pragma unroll
            for (int ni2 = 0; ni2 < 2; ni2++)
                ldsm4(b[2 * ni2][0], b[2 * ni2][1], b[2 * ni2 + 1][0], b[2 * ni2 + 1][1],
                      sb + boff[ni2] + ks * 32);
            #pragma unroll
            for (int mi = 0; mi < 4; mi++)
                #pragma unroll
                for (int ni = 0; ni < 4; ni++)
                    mma16816(acc[mi][ni], a[mi], b[ni]);
        }
        stage = (stage + 1 == NSTAGE) ? 0 : stage + 1;
    }

    // epilogue: bias + store + (optional) fused softmax partials
    int rbase = m0 + wm * 64 + (lane >> 2);
    int cbase = n0 + wn * 32 + 2 * (lane & 3);

    float lm[8], lsv[8];
    #pragma unroll
    for (int k = 0; k < 8; k++) { lm[k] = -1e30f; lsv[k] = 0.0f; }

    #pragma unroll
    for (int mi = 0; mi < 4; mi++) {
        #pragma unroll
        for (int ni = 0; ni < 4; ni++) {
            int col = cbase + ni * 8;
            if (col >= N_real) continue;
            int cl = (wn * 32 + ni * 8 + 2 * (lane & 3));
            float bx = sbias[cl], by = sbias[cl + 1];
            int r0 = rbase + mi * 16;
            float v00 = acc[mi][ni][0] + bx, v01 = acc[mi][ni][1] + by;
            float v10 = acc[mi][ni][2] + bx, v11 = acc[mi][ni][3] + by;
            *reinterpret_cast<float2*>(&C[(size_t)r0 * N_real + col]) = make_float2(v00, v01);
            *reinterpret_cast<float2*>(&C[(size_t)(r0 + 8) * N_real + col]) = make_float2(v10, v11);
            if (do_sm) {
                int g0 = mi * 2, g1 = mi * 2 + 1;
                float cm0 = fmaxf(v00, v01);
                if (cm0 > lm[g0]) { lsv[g0] *= __expf(lm[g0] - cm0); lm[g0] = cm0; }
                lsv[g0] += __expf(v00 - lm[g0]) + __expf(v01 - lm[g0]);
                float cm1 = fmaxf(v10, v11);
                if (cm1 > lm[g1]) { lsv[g1] *= __expf(lm[g1] - cm1); lm[g1] = cm1; }
                lsv[g1] += __expf(v10 - lm[g1]) + __expf(v11 - lm[g1]);
            }
        }
    }

    if (do_sm && n0 < N_real) {
        // reduce across the 4 lanes sharing each row (lane^1, lane^2)
        #pragma unroll
        for (int k = 0; k < 8; k++) {
            #pragma unroll
            for (int d = 1; d <= 2; d <<= 1) {
                float m2 = __shfl_xor_sync(0xFFFFFFFF, lm[k], d);
                float s2 = __shfl_xor_sync(0xFFFFFFFF, lsv[k], d);
                float mm = fmaxf(lm[k], m2);
                lsv[k] = lsv[k] * __expf(lm[k] - mm) + s2 * __expf(m2 - mm);
                lm[k] = mm;
            }
        }
        // cross-warp reduce via (dead) pipeline smem
        float* pm_s = reinterpret_cast<float*>(smem);            // [4][128]
        float* ps_s = pm_s + 512;                                // [4][128]
        __syncthreads();    // all warps done with pipeline smem reads
        if ((lane & 3) == 0) {
            #pragma unroll
            for (int mi = 0; mi < 4; mi++)
                #pragma unroll
                for (int r = 0; r < 2; r++) {
                    int rowl = wm * 64 + mi * 16 + r * 8 + (lane >> 2);
                    pm_s[wn * 128 + rowl] = lm[mi * 2 + r];
                    ps_s[wn * 128 + rowl] = lsv[mi * 2 + r];
                }
        }
        __syncthreads();
        if (tid < 128) {
            float m = -1e30f, s = 0.0f;
            #pragma unroll
            for (int w = 0; w < 4; w++) {
                float m2 = pm_s[w * 128 + tid], s2 = ps_s[w * 128 + tid];
                float mm = fmaxf(m, m2);
                s = s * __expf(m - mm) + s2 * __expf(m2 - mm);
                m = mm;
            }
            int xb = n0 >> 7;
            g_pm[(size_t)(m0 + tid) * NXB + xb] = m;
            g_ps[(size_t)(m0 + tid) * NXB + xb] = s;
        }
    }
}

// ---------------- persistent LSTM layer (tensor-core, 64 blocks) --------------
// 64 blocks x 256 threads (8 warps). Block owns 32 gate-cols
// (c = g*8 + e, col = g*512 + e0 + e, e0 = blk*8). Warp w covers K slice
// [w*64, w*64+64). Wh-slice B-fragments persist in registers.
#define HROWB 1040                       // 512 bf16 + 8 pad, conflict-free ldsm
#define LSM_WH_HI 0                      // 32 rows
#define LSM_WH_LO (32 * HROWB)           // 33280
#define LSM_H_HI  (64 * HROWB)           // 66560, 32 rows
#define LSM_H_LO  (96 * HROWB)           // 99840
#define LSM_RED   (128 * HROWB)          // 133120, 8*1024 floats
#define LSM_GS    (LSM_RED + 8 * 1024 * 4)       // 165888, 1024 floats
#define LSM_CS    (LSM_GS + 1024 * 4)            // 169984, 256 floats
#define LSTM_SMEM (LSM_CS + 1024)                // 171008 bytes

__global__ __launch_bounds__(NTHR, 1)
void lstm_layer_mma(const float* __restrict__ Gx,          // [T*B][2048]
                    const __nv_bfloat16* __restrict__ WhThi,  // [2048][512]
                    const __nv_bfloat16* __restrict__ WhTlo,
                    int rA, int rB, unsigned gen_base)
{
    extern __shared__ __align__(16) char sm[];
    unsigned sbase = (unsigned)__cvta_generic_to_shared(sm);
    float* red = reinterpret_cast<float*>(sm + LSM_RED);
    float* gs  = reinterpret_cast<float*>(sm + LSM_GS);
    float* cs  = reinterpret_cast<float*>(sm + LSM_CS);

    int tid = threadIdx.x;
    int wid = tid >> 5;
    int lane = tid & 31;
    int e0 = blockIdx.x * 8;
    int g  = lane >> 3;
    int lr = lane & 7;

    // one-time: load Wh slice (32 rows: col(c) = (c>>3)*512 + e0 + (c&7))
    #pragma unroll
    for (int q = 0; q < 8; q++) {
        int idx = tid + q * 256;          // 0..2047 over 32 rows x 64 granules
        int c = idx >> 6, kk = idx & 63;
        int grow = (c >> 3) * 512 + e0 + (c & 7);
        cp_async16(sbase + LSM_WH_HI + c * HROWB + kk * 16,
                   WhThi + (size_t)grow * EE + kk * 8);
        cp_async16(sbase + LSM_WH_LO + c * HROWB + kk * 16,
                   WhTlo + (size_t)grow * EE + kk * 8);
    }
    cp_commit();
    cs[tid] = 0.0f;
    cp_wait<0>();
    __syncthreads();

    // persistent B fragments (N=32: 2 ldsm tiles) per K slice (4 k-tiles)
    unsigned Bh[4][8], Bl[4][8];
    #pragma unroll
    for (int kt = 0; kt < 4; kt++) {
        unsigned kb = (unsigned)(wid * 128 + kt * 32);
        #pragma unroll
        for (int ni2 = 0; ni2 < 2; ni2++) {
            unsigned rowoff = (unsigned)((ni2 * 16 + (g >> 1) * 8 + lr) * HROWB
                                         + (g & 1) * 16);
            ldsm4(Bh[kt][ni2 * 4 + 0], Bh[kt][ni2 * 4 + 1],
                  Bh[kt][ni2 * 4 + 2], Bh[kt][ni2 * 4 + 3],
                  sbase + LSM_WH_HI + rowoff + kb);
            ldsm4(Bl[kt][ni2 * 4 + 0], Bl[kt][ni2 * 4 + 1],
                  Bl[kt][ni2 * 4 + 2], Bl[kt][ni2 * 4 + 3],
                  sbase + LSM_WH_LO + rowoff + kb);
        }
    }

    // A-fragment offsets (2 m-tiles of 16 over 32 batches)
    unsigned aoff[2];
    #pragma unroll
    for (int mi = 0; mi < 2; mi++)
        aoff[mi] = (unsigned)((mi * 16 + (g & 1) * 8 + lr) * HROWB + (g >> 1) * 16
                              + wid * 128);

    // per-thread output indices (4 of 1024 gate cells)
    int oc[4], ob[4], ocol[4];
    #pragma unroll
    for (int q = 0; q < 4; q++) {
        int i = tid + q * 256;
        oc[q] = i >> 5; ob[q] = i & 31;
        ocol[q] = (oc[q] >> 3) * 512 + e0 + (oc[q] & 7);
    }

    unsigned mygen = gen_base;

    #pragma unroll 1
    for (int t = 0; t < TT; t++) {
        const __nv_bfloat16* hi_r = g_HpHi + ((t & 1) ? (BB * EE) : 0);
        const __nv_bfloat16* lo_r = g_HpLo + ((t & 1) ? (BB * EE) : 0);
        __nv_bfloat16* hi_w = g_HpHi + ((t & 1) ? 0 : (BB * EE));
        __nv_bfloat16* lo_w = g_HpLo + ((t & 1) ? 0 : (BB * EE));

        float gx[4];
        #pragma unroll
        for (int q = 0; q < 4; q++)
            gx[q] = Gx[(size_t)(t * 32 + ob[q]) * 2048 + ocol[q]];

        if (t > 0) {
            #pragma unroll
            for (int q = 0; q < 8; q++) {
                int idx = tid + q * 256;          // 0..2047
                int m = idx >> 6, kk = idx & 63;
                cp_async16(sbase + LSM_H_HI + m * HROWB + kk * 16,
                           hi_r + (size_t)m * EE + kk * 8);
                cp_async16(sbase + LSM_H_LO + m * HROWB + kk * 16,
                           lo_r + (size_t)m * EE + kk * 8);
            }
            cp_commit();
            cp_wait<0>();
            __syncthreads();

            unsigned Ah[2][4][4], Al[2][4][4];
            #pragma unroll
            for (int mi = 0; mi < 2; mi++)
                #pragma unroll
                for (int kt = 0; kt < 4; kt++) {
                    ldsm4(Ah[mi][kt][0], Ah[mi][kt][1], Ah[mi][kt][2], Ah[mi][kt][3],
                          sbase + LSM_H_HI + aoff[mi] + kt * 32);
                    ldsm4(Al[mi][kt][0], Al[mi][kt][1], Al[mi][kt][2], Al[mi][kt][3],
                          sbase + LSM_H_LO + aoff[mi] + kt * 32);
                }

            float acc[2][4][4];
            #pragma unroll
            for (int mi = 0; mi < 2; mi++)
                #pragma unroll
                for (int ni = 0; ni < 4; ni++)
                    #pragma unroll
                    for (int r = 0; r < 4; r++) acc[mi][ni][r] = 0.0f;

            #pragma unroll
            for (int kt = 0; kt < 4; kt++)
                #pragma unroll
                for (int mi = 0; mi < 2; mi++)
                    #pragma unroll
                    for (int ni = 0; ni < 4; ni++) {
                        mma16816(acc[mi][ni], Ah[mi][kt], &Bh[kt][ni * 2]);
                        mma16816(acc[mi][ni], Al[mi][kt], &Bh[kt][ni * 2]);
                        mma16816(acc[mi][ni], Ah[mi][kt], &Bl[kt][ni * 2]);
                    }

            int rrow = lane >> 2;
            int rcol = 2 * (lane & 3);
            #pragma unroll
            for (int mi = 0; mi < 2; mi++)
                #pragma unroll
                for (int ni = 0; ni < 4; ni++) {
                    int m0r = mi * 16 + rrow;
                    int n0c = ni * 8 + rcol;
                    red[wid * 1024 + n0c * 32 + m0r]           = acc[mi][ni][0];
                    red[wid * 1024 + (n0c + 1) * 32 + m0r]     = acc[mi][ni][1];
                    red[wid * 1024 + n0c * 32 + m0r + 8]       = acc[mi][ni][2];
                    red[wid * 1024 + (n0c + 1) * 32 + m0r + 8] = acc[mi][ni][3];
                }
        }
        __syncthreads();

        #pragma unroll
        for (int q = 0; q < 4; q++) {
            int i = tid + q * 256;
            float s = gx[q];
            if (t > 0) {
                #pragma unroll
                for (int w = 0; w < 8; w++) s += red[w * 1024 + i];
            }
            gs[i] = s;
        }
        __syncthreads();

        {
            int b2 = tid & 31, e2 = tid >> 5;          // e2 0..7
            float iv = gs[(0  + e2) * 32 + b2];
            float jv = gs[(8  + e2) * 32 + b2];
            float fv = gs[(16 + e2) * 32 + b2];
            float ov = gs[(24 + e2) * 32 + b2];
            float cold = cs[tid];
            float cn = sigm(fv + 1.0f) * cold + sigm(iv) * tanhf(jv);
            float hn = sigm(ov) * tanhf(cn);
            cs[tid] = cn;
            __nv_bfloat16 hh = __float2bfloat16(hn);
            __nv_bfloat16 hl = __float2bfloat16(hn - __bfloat162float(hh));
            int he = e0 + e2;
            hi_w[b2 * EE + he] = hh;
            lo_w[b2 * EE + he] = hl;
            size_t row = (size_t)(t * rA + b2 * rB) * EE + he;
            g_Ahi[row] = hh;
            g_Alo[row] = hl;
            __threadfence();
        }
        grid_barrier(mygen);
    }
}

// ---------------- final softmax NLL: reduce per-row partials ----------------
__global__ void softmax_final_kernel(const float* __restrict__ logits,
                                     const int* __restrict__ labels)
{
    int row = blockIdx.x * 8 + (threadIdx.x >> 5);
    int lane = threadIdx.x & 31;
    float m = -1e30f, s = 0.0f;
    for (int i = lane; i < NXB; i += 32) {
        float m2 = g_pm[(size_t)row * NXB + i];
        float s2 = g_ps[(size_t)row * NXB + i];
        float mm = fmaxf(m, m2);
        s = s * __expf(m - mm) + s2 * __expf(m2 - mm);
        m = mm;
    }
    #pragma unroll
    for (int d = 16; d > 0; d >>= 1) {
        float m2 = __shfl_xor_sync(0xFFFFFFFF, m, d);
        float s2 = __shfl_xor_sync(0xFFFFFFFF, s, d);
        float mm = fmaxf(m, m2);
        s = s * __expf(m - mm) + s2 * __expf(m2 - mm);
        m = mm;
    }
    if (lane == 0) {
        float lv = logits[(size_t)row * VV + labels[row]];
        g_nll[row] = m + logf(s) - lv;
    }
}

__global__ void perplexity_kernel(float* __restrict__ out, long long out_size) {
    __shared__ float red[256];
    int tid = threadIdx.x;
    float s = 0.f;
    for (int i = tid; i < MROWS; i += 256) s += g_nll[i];
    red[tid] = s; __syncthreads();
    for (int st = 128; st > 0; st >>= 1) {
        if (tid < st) red[tid] += red[tid + st];
        __syncthreads();
    }
    if (tid == 0 && out_size > (long long)MROWS * VV)
        out[out_size - 1] = expf(red[0] / (float)MROWS);
}

// ---------------- host launch ----------------
extern "C" void kernel_launch(void* const* d_in, const int* in_sizes, int n_in,
                              void* d_out, int out_size)
{
    const int*   inputs = (const int*)  d_in[0];
    const int*   labels = (const int*)  d_in[1];
    const float* Emat   = (const float*)d_in[2];
    const float* Wx0    = (const float*)d_in[3];
    const float* Wh0    = (const float*)d_in[4];
    const float* b0     = (const float*)d_in[5];
    const float* Wx1    = (const float*)d_in[6];
    const float* Wh1    = (const float*)d_in[7];
    const float* b1     = (const float*)d_in[8];
    const float* Wd     = (const float*)d_in[9];
    const float* bd     = (const float*)d_in[10];
    float* out = (float*)d_out;

    float *pG;
    __nv_bfloat16 *pAhi, *pAlo, *pWThi, *pWTlo;
    __nv_bfloat16 *pWh0Thi, *pWh0Tlo, *pWh1Thi, *pWh1Tlo;
    cudaGetSymbolAddress((void**)&pG,   g_G);
    cudaGetSymbolAddress((void**)&pAhi, g_Ahi);
    cudaGetSymbolAddress((void**)&pAlo, g_Alo);
    cudaGetSymbolAddress((void**)&pWThi, g_WThi);
    cudaGetSymbolAddress((void**)&pWTlo, g_WTlo);
    cudaGetSymbolAddress((void**)&pWh0Thi, g_Wh0Thi);
    cudaGetSymbolAddress((void**)&pWh0Tlo, g_Wh0Tlo);
    cudaGetSymbolAddress((void**)&pWh1Thi, g_Wh1Thi);
    cudaGetSymbolAddress((void**)&pWh1Tlo, g_Wh1Tlo);

    cudaFuncSetAttribute(lstm_layer_mma,
                         cudaFuncAttributeMaxDynamicSharedMemorySize, LSTM_SMEM);
    cudaFuncSetAttribute(gemm_mma,
                         cudaFuncAttributeMaxDynamicSharedMemorySize, GEMM_SMEM);

    dim3 tsblk(32, 8);

    // 0) reset barrier state
    init_kernel<<<1, 32>>>();

    // 1) embedding gather -> split bf16 A operand (rows t*32+b)
    embed_kernel<<<(MROWS * (EE / 4) + 255) / 256, 256>>>(inputs, Emat);

    // 1b) recurrent weight transposes
    transpose_split_kernel<<<dim3(GE / 32, 16), tsblk>>>(Wh0, GE, pWh0Thi, pWh0Tlo);
    transpose_split_kernel<<<dim3(GE / 32, 16), tsblk>>>(Wh1, GE, pWh1Thi, pWh1Tlo);

    // 2) Wx0^T split; X0 = xs @ Wx0 + b0 -> g_G
    transpose_split_kernel<<<dim3(GE / 32, 16), tsblk>>>(Wx0, GE, pWThi, pWTlo);
    gemm_mma<<<dim3(GE / 128, MROWS / 128), 256, GEMM_SMEM>>>(pAhi, pAlo, b0, pG, GE, 0);

    // 3) layer-0 persistent scan
    lstm_layer_mma<<<LNBLK, NTHR, LSTM_SMEM>>>(pG, pWh0Thi, pWh0Tlo,
                                               /*rA=*/32, /*rB=*/1, /*gen_base=*/0u);

    // 4) Wx1^T split; X1 = H0 @ Wx1 + b1 -> g_G
    transpose_split_kernel<<<dim3(GE / 32, 16), tsblk>>>(Wx1, GE, pWThi, pWTlo);
    gemm_mma<<<dim3(GE / 128, MROWS / 128), 256, GEMM_SMEM>>>(pAhi, pAlo, b1, pG, GE, 0);

    // 5) layer-1 persistent scan (batch-major rows)
    lstm_layer_mma<<<LNBLK, NTHR, LSTM_SMEM>>>(pG, pWh1Thi, pWh1Tlo,
                                               /*rA=*/1, /*rB=*/TT,
                                               /*gen_base=*/(unsigned)TT);

    // 6) Wd^T split; logits = H1 @ Wd + bd -> d_out, with fused softmax partials
    transpose_split_kernel<<<dim3(NPADV / 32, 16), tsblk>>>(Wd, VV, pWThi, pWTlo);
    gemm_mma<<<dim3(NPADV / 128, MROWS / 128), 256, GEMM_SMEM>>>(pAhi, pAlo, bd, out, VV, 1);

    // 7) final per-row NLL from partials
    softmax_final_kernel<<<MROWS / 8, 256>>>(out, labels);

    // 8) perplexity scalar
    perplexity_kernel<<<1, 256>>>(out, (long long)out_size);
}

// round 14
// speedup vs baseline: 1.0921x; 1.0921x over previous
#include <cuda_runtime.h>
#include <cuda_bf16.h>
#include <cstdint>
#include <math.h>

// Problem dims
#define VV 16000
#define BB 32
#define TT 256
#define EE 512
#define GE 2048          // 4*E
#define MROWS 8192       // B*T
#define NPADV 16128      // 126*128, padded vocab for GEMM tiles
#define NXB 125          // real 128-col blocks in vocab (125*128 = 16000)

#define NBLK 128
#define NTHR 256

// ---------------- scratch (device globals; no allocation allowed) -------------
__device__ __align__(16) float g_G   [(size_t)MROWS * GE];     // x@Wx+b (reused per layer)
__device__ __align__(16) __nv_bfloat16 g_HpHi[2 * BB * EE];    // h ping-pong hi
__device__ __align__(16) __nv_bfloat16 g_HpLo[2 * BB * EE];    // h ping-pong lo
__device__ __align__(16) __nv_bfloat16 g_Ahi[(size_t)MROWS * EE];   // A operand hi
__device__ __align__(16) __nv_bfloat16 g_Alo[(size_t)MROWS * EE];   // A operand lo
__device__ __align__(16) __nv_bfloat16 g_WThi[(size_t)NPADV * EE];  // W^T hi [Npad][512]
__device__ __align__(16) __nv_bfloat16 g_WTlo[(size_t)NPADV * EE];  // W^T lo
__device__ __align__(16) __nv_bfloat16 g_Wh0Thi[(size_t)GE * EE];   // Wh0^T hi
__device__ __align__(16) __nv_bfloat16 g_Wh0Tlo[(size_t)GE * EE];
__device__ __align__(16) __nv_bfloat16 g_Wh1Thi[(size_t)GE * EE];   // Wh1^T hi
__device__ __align__(16) __nv_bfloat16 g_Wh1Tlo[(size_t)GE * EE];
__device__ float g_pm [(size_t)MROWS * NXB];   // per-(row, xblock) softmax max
__device__ float g_ps [(size_t)MROWS * NXB];   // per-(row, xblock) softmax sum
__device__ float g_nll [MROWS];
__device__ unsigned g_bar_cnt;
__device__ unsigned g_bar_gen;

// ---------------- helpers ----------------
__device__ __forceinline__ float sigm(float x) { return 1.0f / (1.0f + expf(-x)); }

__device__ __forceinline__ unsigned ld_acq(const unsigned* p) {
    unsigned v;
    asm volatile("ld.acquire.gpu.u32 %0, [%1];" : "=r"(v) : "l"(p) : "memory");
    return v;
}

__device__ __forceinline__ void cp_async16(unsigned int dst, const void* src) {
    asm volatile("cp.async.cg.shared.global [%0], [%1], 16;" :: "r"(dst), "l"(src));
}
__device__ __forceinline__ void cp_commit() { asm volatile("cp.async.commit_group;"); }
template<int N> __device__ __forceinline__ void cp_wait() {
    asm volatile("cp.async.wait_group %0;" :: "n"(N));
}

__device__ __forceinline__ void grid_barrier(unsigned& mygen) {
    __syncthreads();
    if (threadIdx.x == 0) {
        unsigned a = atomicAdd(&g_bar_cnt, 1u);
        if (a == NBLK - 1) {
            g_bar_cnt = 0u;
            __threadfence();
            atomicAdd(&g_bar_gen, 1u);
        } else {
            while (ld_acq(&g_bar_gen) == mygen) { }
        }
        mygen++;
    }
    __syncthreads();
}

// ---------------- mma.sync helpers (compute_80 PTX — HMMA on sm_103) ----------
__device__ __forceinline__ void ldsm4(unsigned& r0, unsigned& r1, unsigned& r2,
                                      unsigned& r3, unsigned addr) {
    asm volatile("ldmatrix.sync.aligned.m8n8.x4.shared.b16 {%0,%1,%2,%3}, [%4];"
                 : "=r"(r0), "=r"(r1), "=r"(r2), "=r"(r3) : "r"(addr));
}
__device__ __forceinline__ void mma16816(float* d, const unsigned* a, const unsigned* b) {
    asm volatile(
        "mma.sync.aligned.m16n8k16.row.col.f32.bf16.bf16.f32 "
        "{%0,%1,%2,%3}, {%4,%5,%6,%7}, {%8,%9}, {%0,%1,%2,%3};"
        : "+f"(d[0]), "+f"(d[1]), "+f"(d[2]), "+f"(d[3])
        : "r"(a[0]), "r"(a[1]), "r"(a[2]), "r"(a[3]), "r"(b[0]), "r"(b[1]));
}

// ---------------- init: reset barrier state ----------------
__global__ void init_kernel() {
    if (threadIdx.x == 0) { g_bar_cnt = 0u; g_bar_gen = 0u; }
}

// ---------------- embedding gather -> split bf16 A operand ----------------
__global__ void embed_kernel(const int* __restrict__ inputs, const float* __restrict__ Emat) {
    int idx = blockIdx.x * blockDim.x + threadIdx.x;
    if (idx >= MROWS * (EE / 4)) return;
    int r  = idx >> 7;
    int e4 = idx & 127;
    int t = r >> 5;
    int b = r & 31;
    int tok = inputs[b * TT + t];
    float4 v = reinterpret_cast<const float4*>(Emat)[(size_t)tok * 128 + e4];
    size_t base = (size_t)r * EE + e4 * 4;
    __nv_bfloat162 h01 = __floats2bfloat162_rn(v.x, v.y);
    __nv_bfloat162 h23 = __floats2bfloat162_rn(v.z, v.w);
    *reinterpret_cast<__nv_bfloat162*>(&g_Ahi[base])     = h01;
    *reinterpret_cast<__nv_bfloat162*>(&g_Ahi[base + 2]) = h23;
    __nv_bfloat162 l01 = __floats2bfloat162_rn(v.x - __bfloat162float(h01.x),
                                               v.y - __bfloat162float(h01.y));
    __nv_bfloat162 l23 = __floats2bfloat162_rn(v.z - __bfloat162float(h23.x),
                                               v.w - __bfloat162float(h23.y));
    *reinterpret_cast<__nv_bfloat162*>(&g_Alo[base])     = l01;
    *reinterpret_cast<__nv_bfloat162*>(&g_Alo[base + 2]) = l23;
}

// ---------------- weight transpose + bf16 split: W[512][N] -> dst[N][512] -----
__global__ void transpose_split_kernel(const float* __restrict__ W, int N,
                                       __nv_bfloat16* __restrict__ dsthi,
                                       __nv_bfloat16* __restrict__ dstlo) {
    __shared__ float tile[32][33];
    int bx = blockIdx.x * 32;
    int by = blockIdx.y * 32;
    int tx = threadIdx.x;
    int ty = threadIdx.y;
    #pragma unroll
    for (int j = 0; j < 4; j++) {
        int k = by + ty + j * 8;
        int n = bx + tx;
        tile[ty + j * 8][tx] = (n < N) ? W[(size_t)k * N + n] : 0.0f;
    }
    __syncthreads();
    #pragma unroll
    for (int j = 0; j < 4; j++) {
        int n = bx + ty + j * 8;
        int k = by + tx;
        float v = tile[tx][ty + j * 8];
        __nv_bfloat16 h = __float2bfloat16(v);
        dsthi[(size_t)n * EE + k] = h;
        dstlo[(size_t)n * EE + k] = __float2bfloat16(v - __bfloat162float(h));
    }
}

// ---------------- bf16 mma GEMM (Round-9 config) + optional fused softmax -----
#define LDT 72
#define ROWB (LDT * 2)                    // 144
#define TILEA_BYTES (128 * ROWB)          // 18432
#define STAGE_BYTES (2 * TILEA_BYTES)     // 36864
#define NSTAGE 3
#define GEMM_SMEM (NSTAGE * STAGE_BYTES)  // 110592

__global__ __launch_bounds__(256, 2)
void gemm_mma(const __nv_bfloat16* __restrict__ Ahi, const __nv_bfloat16* __restrict__ Alo,
              const float* __restrict__ bias, float* __restrict__ C, int N_real,
              int do_sm)
{
    extern __shared__ __align__(16) char smem[];
    __shared__ float sbias[128];

    int tid = threadIdx.x;
    int wid = tid >> 5;
    int lane = tid & 31;
    int wm = wid & 1;
    int wn = wid >> 1;
    int n0 = blockIdx.x * 128;
    int m0 = blockIdx.y * 128;

    unsigned sbase = (unsigned)__cvta_generic_to_shared(smem);

    for (int i = tid; i < 128; i += 256) {
        int n = n0 + i;
        sbias[i] = (n < N_real) ? bias[n] : 0.0f;
    }

    int g  = lane >> 3;
    int lr = lane & 7;
    unsigned aoff[4];
    #pragma unroll
    for (int mi = 0; mi < 4; mi++)
        aoff[mi] = (unsigned)((wm * 64 + mi * 16 + (g & 1) * 8 + lr) * ROWB
                              + (g >> 1) * 16);
    unsigned boff[2];
    #pragma unroll
    for (int ni2 = 0; ni2 < 2; ni2++)
        boff[ni2] = (unsigned)(TILEA_BYTES + (wn * 32 + ni2 * 16 + (g >> 1) * 8 + lr) * ROWB
                               + (g & 1) * 16);

    float acc[4][4][4];
    #pragma unroll
    for (int i = 0; i < 4; i++)
        #pragma unroll
        for (int j = 0; j < 4; j++)
            #pragma unroll
            for (int r = 0; r < 4; r++) acc[i][j][r] = 0.0f;

    const int NCH = 24;

    auto load_chunk = [&](int c, int stage) {
        int phase = c >> 3;
        int k0 = (c & 7) * 64;
        const __nv_bfloat16* Asrc = (phase == 1) ? Alo : Ahi;
        const __nv_bfloat16* Bsrc = (phase == 2) ? g_WTlo : g_WThi;
        unsigned dstA = sbase + stage * STAGE_BYTES;
        unsigned dstB = dstA + TILEA_BYTES;
        #pragma unroll
        for (int q = 0; q < 8; q++) {
            int idx = tid + q * 256;
            if (idx < 1024) {
                int row = idx >> 3, gg = idx & 7;
                cp_async16(dstA + row * ROWB + gg * 16,
                           Asrc + (size_t)(m0 + row) * EE + k0 + gg * 8);
            } else {
                int idx2 = idx - 1024;
                int row = idx2 >> 3, gg = idx2 & 7;
                cp_async16(dstB + row * ROWB + gg * 16,
                           Bsrc + (size_t)(n0 + row) * EE + k0 + gg * 8);
            }
        }
        cp_commit();
    };

    load_chunk(0, 0);
    load_chunk(1, 1);

    int stage = 0;
    #pragma unroll 1
    for (int c = 0; c < NCH; c++) {
        if (c + 2 < NCH) cp_wait<1>(); else cp_wait<0>();
        __syncthreads();
        if (c + 2 < NCH)
            load_chunk(c + 2, (c + 2) % NSTAGE);

        unsigned sb = sbase + stage * STAGE_BYTES;
        #pragma unroll
        for (int ks = 0; ks < 4; ks++) {
            unsigned a[4][4], b[4][2];
            #pragma unroll
            for (int mi = 0; mi < 4; mi++)
                ldsm4(a[mi][0], a[mi][1], a[mi][2], a[mi][3],
                      sb + aoff[mi] + ks * 32);
            #pragma unroll
            for (int ni2 = 0; ni2 < 2; ni2++)
                ldsm4(b[2 * ni2][0], b[2 * ni2][1], b[2 * ni2 + 1][0], b[2 * ni2 + 1][1],
                      sb + boff[ni2] + ks * 32);
            #pragma unroll
            for (int mi = 0; mi < 4; mi++)
                #pragma unroll
                for (int ni = 0; ni < 4; ni++)
                    mma16816(acc[mi][ni], a[mi], b[ni]);
        }
        stage = (stage + 1 == NSTAGE) ? 0 : stage + 1;
    }

    // epilogue: bias + store + (optional) fused softmax partials
    int rbase = m0 + wm * 64 + (lane >> 2);
    int cbase = n0 + wn * 32 + 2 * (lane & 3);

    float lm[8], lsv[8];
    #pragma unroll
    for (int k = 0; k < 8; k++) { lm[k] = -1e30f; lsv[k] = 0.0f; }

    #pragma unroll
    for (int mi = 0; mi < 4; mi++) {
        #pragma unroll
        for (int ni = 0; ni < 4; ni++) {
            int col = cbase + ni * 8;
            if (col >= N_real) continue;
            int cl = (wn * 32 + ni * 8 + 2 * (lane & 3));
            float bx = sbias[cl], by = sbias[cl + 1];
            int r0 = rbase + mi * 16;
            float v00 = acc[mi][ni][0] + bx, v01 = acc[mi][ni][1] + by;
            float v10 = acc[mi][ni][2] + bx, v11 = acc[mi][ni][3] + by;
            *reinterpret_cast<float2*>(&C[(size_t)r0 * N_real + col]) = make_float2(v00, v01);
            *reinterpret_cast<float2*>(&C[(size_t)(r0 + 8) * N_real + col]) = make_float2(v10, v11);
            if (do_sm) {
                int g0 = mi * 2, g1 = mi * 2 + 1;
                float cm0 = fmaxf(v00, v01);
                if (cm0 > lm[g0]) { lsv[g0] *= __expf(lm[g0] - cm0); lm[g0] = cm0; }
                lsv[g0] += __expf(v00 - lm[g0]) + __expf(v01 - lm[g0]);
                float cm1 = fmaxf(v10, v11);
                if (cm1 > lm[g1]) { lsv[g1] *= __expf(lm[g1] - cm1); lm[g1] = cm1; }
                lsv[g1] += __expf(v10 - lm[g1]) + __expf(v11 - lm[g1]);
            }
        }
    }

    if (do_sm && n0 < N_real) {
        #pragma unroll
        for (int k = 0; k < 8; k++) {
            #pragma unroll
            for (int d = 1; d <= 2; d <<= 1) {
                float m2 = __shfl_xor_sync(0xFFFFFFFF, lm[k], d);
                float s2 = __shfl_xor_sync(0xFFFFFFFF, lsv[k], d);
                float mm = fmaxf(lm[k], m2);
                lsv[k] = lsv[k] * __expf(lm[k] - mm) + s2 * __expf(m2 - mm);
                lm[k] = mm;
            }
        }
        float* pm_s = reinterpret_cast<float*>(smem);            // [4][128]
        float* ps_s = pm_s + 512;                                // [4][128]
        __syncthreads();
        if ((lane & 3) == 0) {
            #pragma unroll
            for (int mi = 0; mi < 4; mi++)
                #pragma unroll
                for (int r = 0; r < 2; r++) {
                    int rowl = wm * 64 + mi * 16 + r * 8 + (lane >> 2);
                    pm_s[wn * 128 + rowl] = lm[mi * 2 + r];
                    ps_s[wn * 128 + rowl] = lsv[mi * 2 + r];
                }
        }
        __syncthreads();
        if (tid < 128) {
            float m = -1e30f, s = 0.0f;
            #pragma unroll
            for (int w = 0; w < 4; w++) {
                float m2 = pm_s[w * 128 + tid], s2 = ps_s[w * 128 + tid];
                float mm = fmaxf(m, m2);
                s = s * __expf(m - mm) + s2 * __expf(m2 - mm);
                m = mm;
            }
            int xb = n0 >> 7;
            g_pm[(size_t)(m0 + tid) * NXB + xb] = m;
            g_ps[(size_t)(m0 + tid) * NXB + xb] = s;
        }
    }
}

// ---------------- persistent LSTM layer (tensor-core, 128 blocks) -------------
// Round-12 proven version: block owns 16 gate-cols (c = g*4+el,
// col = g*512 + e0 + el, e0 = blk*4). Warp w covers K slice [w*64, w*64+64).
#define HROWB 1040                       // 512 bf16 + 8 pad = conflict-free ldsm
#define LSM_WH_HI 0                      // 16 rows
#define LSM_WH_LO (16 * HROWB)           // 16640
#define LSM_H_HI  (32 * HROWB)           // 33280, 32 rows
#define LSM_H_LO  (LSM_H_HI + 32 * HROWB)        // 66560
#define LSM_RED   (LSM_H_LO + 32 * HROWB)        // 99840, 8*512 floats
#define LSM_GS    (LSM_RED + 8 * 512 * 4)        // 116224, 512 floats
#define LSM_CS    (LSM_GS + 512 * 4)             // 118272, 128 floats
#define LSTM_SMEM (LSM_CS + 512)                 // 118784 bytes

__global__ __launch_bounds__(NTHR, 1)
void lstm_layer_mma(const float* __restrict__ Gx,          // [T*B][2048]
                    const __nv_bfloat16* __restrict__ WhThi,  // [2048][512]
                    const __nv_bfloat16* __restrict__ WhTlo,
                    int rA, int rB, unsigned gen_base)
{
    extern __shared__ __align__(16) char sm[];
    unsigned sbase = (unsigned)__cvta_generic_to_shared(sm);
    float* red = reinterpret_cast<float*>(sm + LSM_RED);
    float* gs  = reinterpret_cast<float*>(sm + LSM_GS);
    float* cs  = reinterpret_cast<float*>(sm + LSM_CS);

    int tid = threadIdx.x;
    int wid = tid >> 5;
    int lane = tid & 31;
    int e0 = blockIdx.x * 4;
    int g  = lane >> 3;
    int lr = lane & 7;

    // one-time: load Wh slice (16 rows: col(c) = (c>>2)*512 + e0 + (c&3))
    #pragma unroll
    for (int q = 0; q < 4; q++) {
        int idx = tid + q * 256;
        int c = idx >> 6, kk = idx & 63;
        int grow = (c >> 2) * 512 + e0 + (c & 3);
        cp_async16(sbase + LSM_WH_HI + c * HROWB + kk * 16,
                   WhThi + (size_t)grow * EE + kk * 8);
        cp_async16(sbase + LSM_WH_LO + c * HROWB + kk * 16,
                   WhTlo + (size_t)grow * EE + kk * 8);
    }
    cp_commit();
    if (tid < 128) cs[tid] = 0.0f;
    cp_wait<0>();
    __syncthreads();

    // persistent B fragments for my K slice (4 k-tiles of 16)
    unsigned Bh[4][4], Bl[4][4];
    {
        unsigned rowoff = (unsigned)(((g >> 1) * 8 + lr) * HROWB + (g & 1) * 16);
        #pragma unroll
        for (int kt = 0; kt < 4; kt++) {
            unsigned kb = (unsigned)(wid * 128 + kt * 32);
            ldsm4(Bh[kt][0], Bh[kt][1], Bh[kt][2], Bh[kt][3],
                  sbase + LSM_WH_HI + rowoff + kb);
            ldsm4(Bl[kt][0], Bl[kt][1], Bl[kt][2], Bl[kt][3],
                  sbase + LSM_WH_LO + rowoff + kb);
        }
    }

    unsigned aoff[2];
    #pragma unroll
    for (int mi = 0; mi < 2; mi++)
        aoff[mi] = (unsigned)((mi * 16 + (g & 1) * 8 + lr) * HROWB + (g >> 1) * 16
                              + wid * 128);

    int i1 = tid, i2 = tid + 256;
    int c1 = i1 >> 5, b1 = i1 & 31;
    int c2 = i2 >> 5, b2i = i2 & 31;
    int col1 = (c1 >> 2) * 512 + e0 + (c1 & 3);
    int col2 = (c2 >> 2) * 512 + e0 + (c2 & 3);

    unsigned mygen = gen_base;

    #pragma unroll 1
    for (int t = 0; t < TT; t++) {
        const __nv_bfloat16* hi_r = g_HpHi + ((t & 1) ? (BB * EE) : 0);
        const __nv_bfloat16* lo_r = g_HpLo + ((t & 1) ? (BB * EE) : 0);
        __nv_bfloat16* hi_w = g_HpHi + ((t & 1) ? 0 : (BB * EE));
        __nv_bfloat16* lo_w = g_HpLo + ((t & 1) ? 0 : (BB * EE));

        float gx1 = Gx[(size_t)(t * 32 + b1) * 2048 + col1];
        float gx2 = Gx[(size_t)(t * 32 + b2i) * 2048 + col2];

        if (t > 0) {
            #pragma unroll
            for (int q = 0; q < 8; q++) {
                int idx = tid + q * 256;
                int m = idx >> 6, kk = idx & 63;
                cp_async16(sbase + LSM_H_HI + m * HROWB + kk * 16,
                           hi_r + (size_t)m * EE + kk * 8);
                cp_async16(sbase + LSM_H_LO + m * HROWB + kk * 16,
                           lo_r + (size_t)m * EE + kk * 8);
            }
            cp_commit();
            cp_wait<0>();
            __syncthreads();

            unsigned Ah[2][4][4], Al[2][4][4];
            #pragma unroll
            for (int mi = 0; mi < 2; mi++)
                #pragma unroll
                for (int kt = 0; kt < 4; kt++) {
                    ldsm4(Ah[mi][kt][0], Ah[mi][kt][1], Ah[mi][kt][2], Ah[mi][kt][3],
                          sbase + LSM_H_HI + aoff[mi] + kt * 32);
                    ldsm4(Al[mi][kt][0], Al[mi][kt][1], Al[mi][kt][2], Al[mi][kt][3],
                          sbase + LSM_H_LO + aoff[mi] + kt * 32);
                }

            float acc[2][2][4];
            #pragma unroll
            for (int mi = 0; mi < 2; mi++)
                #pragma unroll
                for (int ni = 0; ni < 2; ni++)
                    #pragma unroll
                    for (int r = 0; r < 4; r++) acc[mi][ni][r] = 0.0f;

            #pragma unroll
            for (int kt = 0; kt < 4; kt++)
                #pragma unroll
                for (int mi = 0; mi < 2; mi++)
                    #pragma unroll
                    for (int ni = 0; ni < 2; ni++) {
                        mma16816(acc[mi][ni], Ah[mi][kt], &Bh[kt][ni * 2]);
                        mma16816(acc[mi][ni], Al[mi][kt], &Bh[kt][ni * 2]);
                        mma16816(acc[mi][ni], Ah[mi][kt], &Bl[kt][ni * 2]);
                    }

            int rrow = lane >> 2;
            int rcol = 2 * (lane & 3);
            #pragma unroll
            for (int mi = 0; mi < 2; mi++)
                #pragma unroll
                for (int ni = 0; ni < 2; ni++) {
                    int m0r = mi * 16 + rrow;
                    int n0c = ni * 8 + rcol;
                    red[wid * 512 + n0c * 32 + m0r]           = acc[mi][ni][0];
                    red[wid * 512 + (n0c + 1) * 32 + m0r]     = acc[mi][ni][1];
                    red[wid * 512 + n0c * 32 + m0r + 8]       = acc[mi][ni][2];
                    red[wid * 512 + (n0c + 1) * 32 + m0r + 8] = acc[mi][ni][3];
                }
        }
        __syncthreads();

        float s1 = gx1, s2 = gx2;
        if (t > 0) {
            #pragma unroll
            for (int w = 0; w < 8; w++) {
                s1 += red[w * 512 + i1];
                s2 += red[w * 512 + i2];
            }
        }
        gs[i1] = s1;
        gs[i2] = s2;
        __syncthreads();

        if (tid < 128) {
            int b2 = tid & 31, e2 = tid >> 5;
            float iv = gs[(0  + e2) * 32 + b2];
            float jv = gs[(4  + e2) * 32 + b2];
            float fv = gs[(8  + e2) * 32 + b2];
            float ov = gs[(12 + e2) * 32 + b2];
            float cold = cs[tid];
            float cn = sigm(fv + 1.0f) * cold + sigm(iv) * tanhf(jv);
            float hn = sigm(ov) * tanhf(cn);
            cs[tid] = cn;
            __nv_bfloat16 hh = __float2bfloat16(hn);
            __nv_bfloat16 hl = __float2bfloat16(hn - __bfloat162float(hh));
            int he = e0 + e2;
            hi_w[b2 * EE + he] = hh;
            lo_w[b2 * EE + he] = hl;
            size_t row = (size_t)(t * rA + b2 * rB) * EE + he;
            g_Ahi[row] = hh;
            g_Alo[row] = hl;
            __threadfence();
        }
        grid_barrier(mygen);
    }
}

// ---------------- final softmax NLL: reduce per-row partials ----------------
__global__ void softmax_final_kernel(const float* __restrict__ logits,
                                     const int* __restrict__ labels)
{
    int row = blockIdx.x * 8 + (threadIdx.x >> 5);
    int lane = threadIdx.x & 31;
    float m = -1e30f, s = 0.0f;
    for (int i = lane; i < NXB; i += 32) {
        float m2 = g_pm[(size_t)row * NXB + i];
        float s2 = g_ps[(size_t)row * NXB + i];
        float mm = fmaxf(m, m2);
        s = s * __expf(m - mm) + s2 * __expf(m2 - mm);
        m = mm;
    }
    #pragma unroll
    for (int d = 16; d > 0; d >>= 1) {
        float m2 = __shfl_xor_sync(0xFFFFFFFF, m, d);
        float s2 = __shfl_xor_sync(0xFFFFFFFF, s, d);
        float mm = fmaxf(m, m2);
        s = s * __expf(m - mm) + s2 * __expf(m2 - mm);
        m = mm;
    }
    if (lane == 0) {
        float lv = logits[(size_t)row * VV + labels[row]];
        g_nll[row] = m + logf(s) - lv;
    }
}

__global__ void perplexity_kernel(float* __restrict__ out, long long out_size) {
    __shared__ float red[256];
    int tid = threadIdx.x;
    float s = 0.f;
    for (int i = tid; i < MROWS; i += 256) s += g_nll[i];
    red[tid] = s; __syncthreads();
    for (int st = 128; st > 0; st >>= 1) {
        if (tid < st) red[tid] += red[tid + st];
        __syncthreads();
    }
    if (tid == 0 && out_size > (long long)MROWS * VV)
        out[out_size - 1] = expf(red[0] / (float)MROWS);
}

// ---------------- host launch ----------------
extern "C" void kernel_launch(void* const* d_in, const int* in_sizes, int n_in,
                              void* d_out, int out_size)
{
    const int*   inputs = (const int*)  d_in[0];
    const int*   labels = (const int*)  d_in[1];
    const float* Emat   = (const float*)d_in[2];
    const float* Wx0    = (const float*)d_in[3];
    const float* Wh0    = (const float*)d_in[4];
    const float* b0     = (const float*)d_in[5];
    const float* Wx1    = (const float*)d_in[6];
    const float* Wh1    = (const float*)d_in[7];
    const float* b1     = (const float*)d_in[8];
    const float* Wd     = (const float*)d_in[9];
    const float* bd     = (const float*)d_in[10];
    float* out = (float*)d_out;

    float *pG;
    __nv_bfloat16 *pAhi, *pAlo, *pWThi, *pWTlo;
    __nv_bfloat16 *pWh0Thi, *pWh0Tlo, *pWh1Thi, *pWh1Tlo;
    cudaGetSymbolAddress((void**)&pG,   g_G);
    cudaGetSymbolAddress((void**)&pAhi, g_Ahi);
    cudaGetSymbolAddress((void**)&pAlo, g_Alo);
    cudaGetSymbolAddress((void**)&pWThi, g_WThi);
    cudaGetSymbolAddress((void**)&pWTlo, g_WTlo);
    cudaGetSymbolAddress((void**)&pWh0Thi, g_Wh0Thi);
    cudaGetSymbolAddress((void**)&pWh0Tlo, g_Wh0Tlo);
    cudaGetSymbolAddress((void**)&pWh1Thi, g_Wh1Thi);
    cudaGetSymbolAddress((void**)&pWh1Tlo, g_Wh1Tlo);

    cudaFuncSetAttribute(lstm_layer_mma,
                         cudaFuncAttributeMaxDynamicSharedMemorySize, LSTM_SMEM);
    cudaFuncSetAttribute(gemm_mma,
                         cudaFuncAttributeMaxDynamicSharedMemorySize, GEMM_SMEM);

    dim3 tsblk(32, 8);

    // 0) reset barrier state
    init_kernel<<<1, 32>>>();

    // 1) embedding gather -> split bf16 A operand (rows t*32+b)
    embed_kernel<<<(MROWS * (EE / 4) + 255) / 256, 256>>>(inputs, Emat);

    // 1b) recurrent weight transposes
    transpose_split_kernel<<<dim3(GE / 32, 16), tsblk>>>(Wh0, GE, pWh0Thi, pWh0Tlo);
    transpose_split_kernel<<<dim3(GE / 32, 16), tsblk>>>(Wh1, GE, pWh1Thi, pWh1Tlo);

    // 2) Wx0^T split; X0 = xs @ Wx0 + b0 -> g_G
    transpose_split_kernel<<<dim3(GE / 32, 16), tsblk>>>(Wx0, GE, pWThi, pWTlo);
    gemm_mma<<<dim3(GE / 128, MROWS / 128), 256, GEMM_SMEM>>>(pAhi, pAlo, b0, pG, GE, 0);

    // 3) layer-0 persistent scan
    lstm_layer_mma<<<NBLK, NTHR, LSTM_SMEM>>>(pG, pWh0Thi, pWh0Tlo,
                                              /*rA=*/32, /*rB=*/1, /*gen_base=*/0u);

    // 4) Wx1^T split; X1 = H0 @ Wx1 + b1 -> g_G
    transpose_split_kernel<<<dim3(GE / 32, 16), tsblk>>>(Wx1, GE, pWThi, pWTlo);
    gemm_mma<<<dim3(GE / 128, MROWS / 128), 256, GEMM_SMEM>>>(pAhi, pAlo, b1, pG, GE, 0);

    // 5) layer-1 persistent scan (batch-major rows)
    lstm_layer_mma<<<NBLK, NTHR, LSTM_SMEM>>>(pG, pWh1Thi, pWh1Tlo,
                                              /*rA=*/1, /*rB=*/TT,
                                              /*gen_base=*/(unsigned)TT);

    // 6) Wd^T split; logits = H1 @ Wd + bd -> d_out, with fused softmax partials
    transpose_split_kernel<<<dim3(NPADV / 32, 16), tsblk>>>(Wd, VV, pWThi, pWTlo);
    gemm_mma<<<dim3(NPADV / 128, MROWS / 128), 256, GEMM_SMEM>>>(pAhi, pAlo, bd, out, VV, 1);

    // 7) final per-row NLL from partials
    softmax_final_kernel<<<MROWS / 8, 256>>>(out, labels);

    // 8) perplexity scalar
    perplexity_kernel<<<1, 256>>>(out, (long long)out_size);
}

// round 15
// speedup vs baseline: 1.1060x; 1.0127x over previous
#include <cuda_runtime.h>
#include <cuda_bf16.h>
#include <cstdint>
#include <math.h>

// Problem dims
#define VV 16000
#define BB 32
#define TT 256
#define EE 512
#define GE 2048          // 4*E
#define MROWS 8192       // B*T
#define NPADV 16128      // 126*128, padded vocab for GEMM tiles
#define NXB 125          // real 128-col blocks in vocab (125*128 = 16000)

#define NBLK 128
#define NTHR 256

// ---------------- scratch (device globals; no allocation allowed) -------------
__device__ __align__(16) float g_G   [(size_t)MROWS * GE];     // x@Wx+b (reused per layer)
__device__ __align__(16) __nv_bfloat16 g_HpHi[2 * BB * EE];    // h ping-pong hi
__device__ __align__(16) __nv_bfloat16 g_HpLo[2 * BB * EE];    // h ping-pong lo
__device__ __align__(16) __nv_bfloat16 g_Ahi[(size_t)MROWS * EE];   // A operand hi
__device__ __align__(16) __nv_bfloat16 g_Alo[(size_t)MROWS * EE];   // A operand lo
__device__ __align__(16) __nv_bfloat16 g_WThi[(size_t)NPADV * EE];  // W^T hi [Npad][512]
__device__ __align__(16) __nv_bfloat16 g_WTlo[(size_t)NPADV * EE];  // W^T lo
__device__ __align__(16) __nv_bfloat16 g_Wh0Thi[(size_t)GE * EE];   // Wh0^T hi
__device__ __align__(16) __nv_bfloat16 g_Wh0Tlo[(size_t)GE * EE];
__device__ __align__(16) __nv_bfloat16 g_Wh1Thi[(size_t)GE * EE];   // Wh1^T hi
__device__ __align__(16) __nv_bfloat16 g_Wh1Tlo[(size_t)GE * EE];
__device__ float g_pm [(size_t)MROWS * NXB];   // per-(row, xblock) softmax max
__device__ float g_ps [(size_t)MROWS * NXB];   // per-(row, xblock) softmax sum
__device__ float g_nll [MROWS];
__device__ unsigned g_bar_cnt;
__device__ unsigned g_bar_gen;

// ---------------- helpers ----------------
__device__ __forceinline__ float sigm(float x) { return 1.0f / (1.0f + expf(-x)); }

__device__ __forceinline__ unsigned ld_acq(const unsigned* p) {
    unsigned v;
    asm volatile("ld.acquire.gpu.u32 %0, [%1];" : "=r"(v) : "l"(p) : "memory");
    return v;
}

__device__ __forceinline__ void cp_async16(unsigned int dst, const void* src) {
    asm volatile("cp.async.cg.shared.global [%0], [%1], 16;" :: "r"(dst), "l"(src));
}
__device__ __forceinline__ void cp_commit() { asm volatile("cp.async.commit_group;"); }
template<int N> __device__ __forceinline__ void cp_wait() {
    asm volatile("cp.async.wait_group %0;" :: "n"(N));
}

__device__ __forceinline__ void grid_barrier(unsigned& mygen) {
    __syncthreads();
    if (threadIdx.x == 0) {
        unsigned a = atomicAdd(&g_bar_cnt, 1u);
        if (a == NBLK - 1) {
            g_bar_cnt = 0u;
            __threadfence();
            atomicAdd(&g_bar_gen, 1u);
        } else {
            while (ld_acq(&g_bar_gen) == mygen) { }
        }
        mygen++;
    }
    __syncthreads();
}

// ---------------- mma.sync helpers (compute_80 PTX — HMMA on sm_103) ----------
__device__ __forceinline__ void ldsm4(unsigned& r0, unsigned& r1, unsigned& r2,
                                      unsigned& r3, unsigned addr) {
    asm volatile("ldmatrix.sync.aligned.m8n8.x4.shared.b16 {%0,%1,%2,%3}, [%4];"
                 : "=r"(r0), "=r"(r1), "=r"(r2), "=r"(r3) : "r"(addr));
}
__device__ __forceinline__ void mma16816(float* d, const unsigned* a, const unsigned* b) {
    asm volatile(
        "mma.sync.aligned.m16n8k16.row.col.f32.bf16.bf16.f32 "
        "{%0,%1,%2,%3}, {%4,%5,%6,%7}, {%8,%9}, {%0,%1,%2,%3};"
        : "+f"(d[0]), "+f"(d[1]), "+f"(d[2]), "+f"(d[3])
        : "r"(a[0]), "r"(a[1]), "r"(a[2]), "r"(a[3]), "r"(b[0]), "r"(b[1]));
}

// ---------------- init: reset barrier state ----------------
__global__ void init_kernel() {
    if (threadIdx.x == 0) { g_bar_cnt = 0u; g_bar_gen = 0u; }
}

// ---------------- embedding gather -> split bf16 A operand ----------------
__global__ void embed_kernel(const int* __restrict__ inputs, const float* __restrict__ Emat) {
    int idx = blockIdx.x * blockDim.x + threadIdx.x;
    if (idx >= MROWS * (EE / 4)) return;
    int r  = idx >> 7;
    int e4 = idx & 127;
    int t = r >> 5;
    int b = r & 31;
    int tok = inputs[b * TT + t];
    float4 v = reinterpret_cast<const float4*>(Emat)[(size_t)tok * 128 + e4];
    size_t base = (size_t)r * EE + e4 * 4;
    __nv_bfloat162 h01 = __floats2bfloat162_rn(v.x, v.y);
    __nv_bfloat162 h23 = __floats2bfloat162_rn(v.z, v.w);
    *reinterpret_cast<__nv_bfloat162*>(&g_Ahi[base])     = h01;
    *reinterpret_cast<__nv_bfloat162*>(&g_Ahi[base + 2]) = h23;
    __nv_bfloat162 l01 = __floats2bfloat162_rn(v.x - __bfloat162float(h01.x),
                                               v.y - __bfloat162float(h01.y));
    __nv_bfloat162 l23 = __floats2bfloat162_rn(v.z - __bfloat162float(h23.x),
                                               v.w - __bfloat162float(h23.y));
    *reinterpret_cast<__nv_bfloat162*>(&g_Alo[base])     = l01;
    *reinterpret_cast<__nv_bfloat162*>(&g_Alo[base + 2]) = l23;
}

// ---------------- weight transpose + bf16 split: W[512][N] -> dst[N][512] -----
__global__ void transpose_split_kernel(const float* __restrict__ W, int N,
                                       __nv_bfloat16* __restrict__ dsthi,
                                       __nv_bfloat16* __restrict__ dstlo) {
    __shared__ float tile[32][33];
    int bx = blockIdx.x * 32;
    int by = blockIdx.y * 32;
    int tx = threadIdx.x;
    int ty = threadIdx.y;
    #pragma unroll
    for (int j = 0; j < 4; j++) {
        int k = by + ty + j * 8;
        int n = bx + tx;
        tile[ty + j * 8][tx] = (n < N) ? W[(size_t)k * N + n] : 0.0f;
    }
    __syncthreads();
    #pragma unroll
    for (int j = 0; j < 4; j++) {
        int n = bx + ty + j * 8;
        int k = by + tx;
        float v = tile[tx][ty + j * 8];
        __nv_bfloat16 h = __float2bfloat16(v);
        dsthi[(size_t)n * EE + k] = h;
        dstlo[(size_t)n * EE + k] = __float2bfloat16(v - __bfloat162float(h));
    }
}

// ---------------- bf16 mma GEMM, phase-fused chunks + optional fused softmax --
// Each chunk = K=32 slice with all 4 tiles (Ahi, Alo, Bhi, Blo) resident;
// all 3 split phases (Ah*Bh, Al*Bh, Ah*Bl) computed per chunk. Each operand
// is streamed exactly once. Tile 128x128, 256 thr (8 warps, 2m x 4n, 64x32).
#define LDT 40                            // bf16 per smem row (80 B, conflict-free)
#define ROWB (LDT * 2)                    // 80
#define TILE_B (128 * ROWB)               // 10240 per tile
#define T_AHI 0
#define T_ALO TILE_B
#define T_BHI (2 * TILE_B)
#define T_BLO (3 * TILE_B)
#define STAGE_BYTES (4 * TILE_B)          // 40960
#define GEMM_SMEM (2 * STAGE_BYTES)       // 81920

__global__ __launch_bounds__(256, 2)
void gemm_mma(const __nv_bfloat16* __restrict__ Ahi, const __nv_bfloat16* __restrict__ Alo,
              const float* __restrict__ bias, float* __restrict__ C, int N_real,
              int do_sm)
{
    extern __shared__ __align__(16) char smem[];
    __shared__ float sbias[128];

    int tid = threadIdx.x;
    int wid = tid >> 5;
    int lane = tid & 31;
    int wm = wid & 1;
    int wn = wid >> 1;
    int n0 = blockIdx.x * 128;
    int m0 = blockIdx.y * 128;

    unsigned sbase = (unsigned)__cvta_generic_to_shared(smem);

    for (int i = tid; i < 128; i += 256) {
        int n = n0 + i;
        sbias[i] = (n < N_real) ? bias[n] : 0.0f;
    }

    int g  = lane >> 3;
    int lr = lane & 7;
    unsigned aoff[4];
    #pragma unroll
    for (int mi = 0; mi < 4; mi++)
        aoff[mi] = (unsigned)((wm * 64 + mi * 16 + (g & 1) * 8 + lr) * ROWB
                              + (g >> 1) * 16);
    unsigned boff[2];
    #pragma unroll
    for (int ni2 = 0; ni2 < 2; ni2++)
        boff[ni2] = (unsigned)((wn * 32 + ni2 * 16 + (g >> 1) * 8 + lr) * ROWB
                               + (g & 1) * 16);

    float acc[4][4][4];
    #pragma unroll
    for (int i = 0; i < 4; i++)
        #pragma unroll
        for (int j = 0; j < 4; j++)
            #pragma unroll
            for (int r = 0; r < 4; r++) acc[i][j][r] = 0.0f;

    const int NCH = 16;   // 16 K-slices of 32

    auto load_chunk = [&](int c, int stage) {
        int k0 = c * 32;
        unsigned dst = sbase + stage * STAGE_BYTES;
        #pragma unroll
        for (int q = 0; q < 8; q++) {
            int idx = tid + q * 256;          // 0..2047
            int tile = idx >> 9;              // 0..3
            int row  = (idx >> 2) & 127;
            int gg   = idx & 3;
            const __nv_bfloat16* src;
            int grow;
            if (tile == 0)      { src = Ahi;    grow = m0 + row; }
            else if (tile == 1) { src = Alo;    grow = m0 + row; }
            else if (tile == 2) { src = g_WThi; grow = n0 + row; }
            else                { src = g_WTlo; grow = n0 + row; }
            cp_async16(dst + tile * TILE_B + row * ROWB + gg * 16,
                       src + (size_t)grow * EE + k0 + gg * 8);
        }
        cp_commit();
    };

    load_chunk(0, 0);
    load_chunk(1, 1);

    #pragma unroll 1
    for (int c = 0; c < NCH; c++) {
        if (c + 1 < NCH) cp_wait<1>(); else cp_wait<0>();
        __syncthreads();

        unsigned sb = sbase + (c & 1) * STAGE_BYTES;
        #pragma unroll
        for (int ks = 0; ks < 2; ks++) {
            unsigned ah[4][4], al[4][4], bh[4][2], bl[4][2];
            #pragma unroll
            for (int mi = 0; mi < 4; mi++) {
                ldsm4(ah[mi][0], ah[mi][1], ah[mi][2], ah[mi][3],
                      sb + T_AHI + aoff[mi] + ks * 32);
                ldsm4(al[mi][0], al[mi][1], al[mi][2], al[mi][3],
                      sb + T_ALO + aoff[mi] + ks * 32);
            }
            #pragma unroll
            for (int ni2 = 0; ni2 < 2; ni2++) {
                ldsm4(bh[2 * ni2][0], bh[2 * ni2][1], bh[2 * ni2 + 1][0], bh[2 * ni2 + 1][1],
                      sb + T_BHI + boff[ni2] + ks * 32);
                ldsm4(bl[2 * ni2][0], bl[2 * ni2][1], bl[2 * ni2 + 1][0], bl[2 * ni2 + 1][1],
                      sb + T_BLO + boff[ni2] + ks * 32);
            }
            #pragma unroll
            for (int mi = 0; mi < 4; mi++)
                #pragma unroll
                for (int ni = 0; ni < 4; ni++) {
                    mma16816(acc[mi][ni], ah[mi], bh[ni]);
                    mma16816(acc[mi][ni], al[mi], bh[ni]);
                    mma16816(acc[mi][ni], ah[mi], bl[ni]);
                }
        }
        __syncthreads();
        if (c + 2 < NCH)
            load_chunk(c + 2, c & 1);
    }

    // epilogue: bias + store + (optional) fused softmax partials
    int rbase = m0 + wm * 64 + (lane >> 2);
    int cbase = n0 + wn * 32 + 2 * (lane & 3);

    float lm[8], lsv[8];
    #pragma unroll
    for (int k = 0; k < 8; k++) { lm[k] = -1e30f; lsv[k] = 0.0f; }

    #pragma unroll
    for (int mi = 0; mi < 4; mi++) {
        #pragma unroll
        for (int ni = 0; ni < 4; ni++) {
            int col = cbase + ni * 8;
            if (col >= N_real) continue;
            int cl = (wn * 32 + ni * 8 + 2 * (lane & 3));
            float bx = sbias[cl], by = sbias[cl + 1];
            int r0 = rbase + mi * 16;
            float v00 = acc[mi][ni][0] + bx, v01 = acc[mi][ni][1] + by;
            float v10 = acc[mi][ni][2] + bx, v11 = acc[mi][ni][3] + by;
            *reinterpret_cast<float2*>(&C[(size_t)r0 * N_real + col]) = make_float2(v00, v01);
            *reinterpret_cast<float2*>(&C[(size_t)(r0 + 8) * N_real + col]) = make_float2(v10, v11);
            if (do_sm) {
                int g0 = mi * 2, g1 = mi * 2 + 1;
                float cm0 = fmaxf(v00, v01);
                if (cm0 > lm[g0]) { lsv[g0] *= __expf(lm[g0] - cm0); lm[g0] = cm0; }
                lsv[g0] += __expf(v00 - lm[g0]) + __expf(v01 - lm[g0]);
                float cm1 = fmaxf(v10, v11);
                if (cm1 > lm[g1]) { lsv[g1] *= __expf(lm[g1] - cm1); lm[g1] = cm1; }
                lsv[g1] += __expf(v10 - lm[g1]) + __expf(v11 - lm[g1]);
            }
        }
    }

    if (do_sm && n0 < N_real) {
        #pragma unroll
        for (int k = 0; k < 8; k++) {
            #pragma unroll
            for (int d = 1; d <= 2; d <<= 1) {
                float m2 = __shfl_xor_sync(0xFFFFFFFF, lm[k], d);
                float s2 = __shfl_xor_sync(0xFFFFFFFF, lsv[k], d);
                float mm = fmaxf(lm[k], m2);
                lsv[k] = lsv[k] * __expf(lm[k] - mm) + s2 * __expf(m2 - mm);
                lm[k] = mm;
            }
        }
        float* pm_s = reinterpret_cast<float*>(smem);            // [4][128]
        float* ps_s = pm_s + 512;                                // [4][128]
        __syncthreads();
        if ((lane & 3) == 0) {
            #pragma unroll
            for (int mi = 0; mi < 4; mi++)
                #pragma unroll
                for (int r = 0; r < 2; r++) {
                    int rowl = wm * 64 + mi * 16 + r * 8 + (lane >> 2);
                    pm_s[wn * 128 + rowl] = lm[mi * 2 + r];
                    ps_s[wn * 128 + rowl] = lsv[mi * 2 + r];
                }
        }
        __syncthreads();
        if (tid < 128) {
            float m = -1e30f, s = 0.0f;
            #pragma unroll
            for (int w = 0; w < 4; w++) {
                float m2 = pm_s[w * 128 + tid], s2 = ps_s[w * 128 + tid];
                float mm = fmaxf(m, m2);
                s = s * __expf(m - mm) + s2 * __expf(m2 - mm);
                m = mm;
            }
            int xb = n0 >> 7;
            g_pm[(size_t)(m0 + tid) * NXB + xb] = m;
            g_ps[(size_t)(m0 + tid) * NXB + xb] = s;
        }
    }
}

// ---------------- persistent LSTM layer (tensor-core, 128 blocks) -------------
#define HROWB 1040                       // 512 bf16 + 8 pad = conflict-free ldsm
#define LSM_WH_HI 0                      // 16 rows
#define LSM_WH_LO (16 * HROWB)           // 16640
#define LSM_H_HI  (32 * HROWB)           // 33280, 32 rows
#define LSM_H_LO  (LSM_H_HI + 32 * HROWB)        // 66560
#define LSM_RED   (LSM_H_LO + 32 * HROWB)        // 99840, 8*512 floats
#define LSM_GS    (LSM_RED + 8 * 512 * 4)        // 116224, 512 floats
#define LSM_CS    (LSM_GS + 512 * 4)             // 118272, 128 floats
#define LSTM_SMEM (LSM_CS + 512)                 // 118784 bytes

__global__ __launch_bounds__(NTHR, 1)
void lstm_layer_mma(const float* __restrict__ Gx,          // [T*B][2048]
                    const __nv_bfloat16* __restrict__ WhThi,  // [2048][512]
                    const __nv_bfloat16* __restrict__ WhTlo,
                    int rA, int rB, unsigned gen_base)
{
    extern __shared__ __align__(16) char sm[];
    unsigned sbase = (unsigned)__cvta_generic_to_shared(sm);
    float* red = reinterpret_cast<float*>(sm + LSM_RED);
    float* gs  = reinterpret_cast<float*>(sm + LSM_GS);
    float* cs  = reinterpret_cast<float*>(sm + LSM_CS);

    int tid = threadIdx.x;
    int wid = tid >> 5;
    int lane = tid & 31;
    int e0 = blockIdx.x * 4;
    int g  = lane >> 3;
    int lr = lane & 7;

    #pragma unroll
    for (int q = 0; q < 4; q++) {
        int idx = tid + q * 256;
        int c = idx >> 6, kk = idx & 63;
        int grow = (c >> 2) * 512 + e0 + (c & 3);
        cp_async16(sbase + LSM_WH_HI + c * HROWB + kk * 16,
                   WhThi + (size_t)grow * EE + kk * 8);
        cp_async16(sbase + LSM_WH_LO + c * HROWB + kk * 16,
                   WhTlo + (size_t)grow * EE + kk * 8);
    }
    cp_commit();
    if (tid < 128) cs[tid] = 0.0f;
    cp_wait<0>();
    __syncthreads();

    unsigned Bh[4][4], Bl[4][4];
    {
        unsigned rowoff = (unsigned)(((g >> 1) * 8 + lr) * HROWB + (g & 1) * 16);
        #pragma unroll
        for (int kt = 0; kt < 4; kt++) {
            unsigned kb = (unsigned)(wid * 128 + kt * 32);
            ldsm4(Bh[kt][0], Bh[kt][1], Bh[kt][2], Bh[kt][3],
                  sbase + LSM_WH_HI + rowoff + kb);
            ldsm4(Bl[kt][0], Bl[kt][1], Bl[kt][2], Bl[kt][3],
                  sbase + LSM_WH_LO + rowoff + kb);
        }
    }

    unsigned aoff2[2];
    #pragma unroll
    for (int mi = 0; mi < 2; mi++)
        aoff2[mi] = (unsigned)((mi * 16 + (g & 1) * 8 + lr) * HROWB + (g >> 1) * 16
                               + wid * 128);

    int i1 = tid, i2 = tid + 256;
    int c1 = i1 >> 5, b1 = i1 & 31;
    int c2 = i2 >> 5, b2i = i2 & 31;
    int col1 = (c1 >> 2) * 512 + e0 + (c1 & 3);
    int col2 = (c2 >> 2) * 512 + e0 + (c2 & 3);

    unsigned mygen = gen_base;

    #pragma unroll 1
    for (int t = 0; t < TT; t++) {
        const __nv_bfloat16* hi_r = g_HpHi + ((t & 1) ? (BB * EE) : 0);
        const __nv_bfloat16* lo_r = g_HpLo + ((t & 1) ? (BB * EE) : 0);
        __nv_bfloat16* hi_w = g_HpHi + ((t & 1) ? 0 : (BB * EE));
        __nv_bfloat16* lo_w = g_HpLo + ((t & 1) ? 0 : (BB * EE));

        float gx1 = Gx[(size_t)(t * 32 + b1) * 2048 + col1];
        float gx2 = Gx[(size_t)(t * 32 + b2i) * 2048 + col2];

        if (t > 0) {
            #pragma unroll
            for (int q = 0; q < 8; q++) {
                int idx = tid + q * 256;
                int m = idx >> 6, kk = idx & 63;
                cp_async16(sbase + LSM_H_HI + m * HROWB + kk * 16,
                           hi_r + (size_t)m * EE + kk * 8);
                cp_async16(sbase + LSM_H_LO + m * HROWB + kk * 16,
                           lo_r + (size_t)m * EE + kk * 8);
            }
            cp_commit();
            cp_wait<0>();
            __syncthreads();

            unsigned Ah[2][4][4], Al[2][4][4];
            #pragma unroll
            for (int mi = 0; mi < 2; mi++)
                #pragma unroll
                for (int kt = 0; kt < 4; kt++) {
                    ldsm4(Ah[mi][kt][0], Ah[mi][kt][1], Ah[mi][kt][2], Ah[mi][kt][3],
                          sbase + LSM_H_HI + aoff2[mi] + kt * 32);
                    ldsm4(Al[mi][kt][0], Al[mi][kt][1], Al[mi][kt][2], Al[mi][kt][3],
                          sbase + LSM_H_LO + aoff2[mi] + kt * 32);
                }

            float acc[2][2][4];
            #pragma unroll
            for (int mi = 0; mi < 2; mi++)
                #pragma unroll
                for (int ni = 0; ni < 2; ni++)
                    #pragma unroll
                    for (int r = 0; r < 4; r++) acc[mi][ni][r] = 0.0f;

            #pragma unroll
            for (int kt = 0; kt < 4; kt++)
                #pragma unroll
                for (int mi = 0; mi < 2; mi++)
                    #pragma unroll
                    for (int ni = 0; ni < 2; ni++) {
                        mma16816(acc[mi][ni], Ah[mi][kt], &Bh[kt][ni * 2]);
                        mma16816(acc[mi][ni], Al[mi][kt], &Bh[kt][ni * 2]);
                        mma16816(acc[mi][ni], Ah[mi][kt], &Bl[kt][ni * 2]);
                    }

            int rrow = lane >> 2;
            int rcol = 2 * (lane & 3);
            #pragma unroll
            for (int mi = 0; mi < 2; mi++)
                #pragma unroll
                for (int ni = 0; ni < 2; ni++) {
                    int m0r = mi * 16 + rrow;
                    int n0c = ni * 8 + rcol;
                    red[wid * 512 + n0c * 32 + m0r]           = acc[mi][ni][0];
                    red[wid * 512 + (n0c + 1) * 32 + m0r]     = acc[mi][ni][1];
                    red[wid * 512 + n0c * 32 + m0r + 8]       = acc[mi][ni][2];
                    red[wid * 512 + (n0c + 1) * 32 + m0r + 8] = acc[mi][ni][3];
                }
        }
        __syncthreads();

        float s1 = gx1, s2 = gx2;
        if (t > 0) {
            #pragma unroll
            for (int w = 0; w < 8; w++) {
                s1 += red[w * 512 + i1];
                s2 += red[w * 512 + i2];
            }
        }
        gs[i1] = s1;
        gs[i2] = s2;
        __syncthreads();

        if (tid < 128) {
            int b2 = tid & 31, e2 = tid >> 5;
            float iv = gs[(0  + e2) * 32 + b2];
            float jv = gs[(4  + e2) * 32 + b2];
            float fv = gs[(8  + e2) * 32 + b2];
            float ov = gs[(12 + e2) * 32 + b2];
            float cold = cs[tid];
            float cn = sigm(fv + 1.0f) * cold + sigm(iv) * tanhf(jv);
            float hn = sigm(ov) * tanhf(cn);
            cs[tid] = cn;
            __nv_bfloat16 hh = __float2bfloat16(hn);
            __nv_bfloat16 hl = __float2bfloat16(hn - __bfloat162float(hh));
            int he = e0 + e2;
            hi_w[b2 * EE + he] = hh;
            lo_w[b2 * EE + he] = hl;
            size_t row = (size_t)(t * rA + b2 * rB) * EE + he;
            g_Ahi[row] = hh;
            g_Alo[row] = hl;
            __threadfence();
        }
        grid_barrier(mygen);
    }
}

// ---------------- final softmax NLL: reduce per-row partials ----------------
__global__ void softmax_final_kernel(const float* __restrict__ logits,
                                     const int* __restrict__ labels)
{
    int row = blockIdx.x * 8 + (threadIdx.x >> 5);
    int lane = threadIdx.x & 31;
    float m = -1e30f, s = 0.0f;
    for (int i = lane; i < NXB; i += 32) {
        float m2 = g_pm[(size_t)row * NXB + i];
        float s2 = g_ps[(size_t)row * NXB + i];
        float mm = fmaxf(m, m2);
        s = s * __expf(m - mm) + s2 * __expf(m2 - mm);
        m = mm;
    }
    #pragma unroll
    for (int d = 16; d > 0; d >>= 1) {
        float m2 = __shfl_xor_sync(0xFFFFFFFF, m, d);
        float s2 = __shfl_xor_sync(0xFFFFFFFF, s, d);
        float mm = fmaxf(m, m2);
        s = s * __expf(m - mm) + s2 * __expf(m2 - mm);
        m = mm;
    }
    if (lane == 0) {
        float lv = logits[(size_t)row * VV + labels[row]];
        g_nll[row] = m + logf(s) - lv;
    }
}

__global__ void perplexity_kernel(float* __restrict__ out, long long out_size) {
    __shared__ float red[256];
    int tid = threadIdx.x;
    float s = 0.f;
    for (int i = tid; i < MROWS; i += 256) s += g_nll[i];
    red[tid] = s; __syncthreads();
    for (int st = 128; st > 0; st >>= 1) {
        if (tid < st) red[tid] += red[tid + st];
        __syncthreads();
    }
    if (tid == 0 && out_size > (long long)MROWS * VV)
        out[out_size - 1] = expf(red[0] / (float)MROWS);
}

// ---------------- host launch ----------------
extern "C" void kernel_launch(void* const* d_in, const int* in_sizes, int n_in,
                              void* d_out, int out_size)
{
    const int*   inputs = (const int*)  d_in[0];
    const int*   labels = (const int*)  d_in[1];
    const float* Emat   = (const float*)d_in[2];
    const float* Wx0    = (const float*)d_in[3];
    const float* Wh0    = (const float*)d_in[4];
    const float* b0     = (const float*)d_in[5];
    const float* Wx1    = (const float*)d_in[6];
    const float* Wh1    = (const float*)d_in[7];
    const float* b1     = (const float*)d_in[8];
    const float* Wd     = (const float*)d_in[9];
    const float* bd     = (const float*)d_in[10];
    float* out = (float*)d_out;

    float *pG;
    __nv_bfloat16 *pAhi, *pAlo, *pWThi, *pWTlo;
    __nv_bfloat16 *pWh0Thi, *pWh0Tlo, *pWh1Thi, *pWh1Tlo;
    cudaGetSymbolAddress((void**)&pG,   g_G);
    cudaGetSymbolAddress((void**)&pAhi, g_Ahi);
    cudaGetSymbolAddress((void**)&pAlo, g_Alo);
    cudaGetSymbolAddress((void**)&pWThi, g_WThi);
    cudaGetSymbolAddress((void**)&pWTlo, g_WTlo);
    cudaGetSymbolAddress((void**)&pWh0Thi, g_Wh0Thi);
    cudaGetSymbolAddress((void**)&pWh0Tlo, g_Wh0Tlo);
    cudaGetSymbolAddress((void**)&pWh1Thi, g_Wh1Thi);
    cudaGetSymbolAddress((void**)&pWh1Tlo, g_Wh1Tlo);

    cudaFuncSetAttribute(lstm_layer_mma,
                         cudaFuncAttributeMaxDynamicSharedMemorySize, LSTM_SMEM);
    cudaFuncSetAttribute(gemm_mma,
                         cudaFuncAttributeMaxDynamicSharedMemorySize, GEMM_SMEM);

    dim3 tsblk(32, 8);

    // 0) reset barrier state
    init_kernel<<<1, 32>>>();

    // 1) embedding gather -> split bf16 A operand (rows t*32+b)
    embed_kernel<<<(MROWS * (EE / 4) + 255) / 256, 256>>>(inputs, Emat);

    // 1b) recurrent weight transposes
    transpose_split_kernel<<<dim3(GE / 32, 16), tsblk>>>(Wh0, GE, pWh0Thi, pWh0Tlo);
    transpose_split_kernel<<<dim3(GE / 32, 16), tsblk>>>(Wh1, GE, pWh1Thi, pWh1Tlo);

    // 2) Wx0^T split; X0 = xs @ Wx0 + b0 -> g_G
    transpose_split_kernel<<<dim3(GE / 32, 16), tsblk>>>(Wx0, GE, pWThi, pWTlo);
    gemm_mma<<<dim3(GE / 128, MROWS / 128), 256, GEMM_SMEM>>>(pAhi, pAlo, b0, pG, GE, 0);

    // 3) layer-0 persistent scan
    lstm_layer_mma<<<NBLK, NTHR, LSTM_SMEM>>>(pG, pWh0Thi, pWh0Tlo,
                                              /*rA=*/32, /*rB=*/1, /*gen_base=*/0u);

    // 4) Wx1^T split; X1 = H0 @ Wx1 + b1 -> g_G
    transpose_split_kernel<<<dim3(GE / 32, 16), tsblk>>>(Wx1, GE, pWThi, pWTlo);
    gemm_mma<<<dim3(GE / 128, MROWS / 128), 256, GEMM_SMEM>>>(pAhi, pAlo, b1, pG, GE, 0);

    // 5) layer-1 persistent scan (batch-major rows)
    lstm_layer_mma<<<NBLK, NTHR, LSTM_SMEM>>>(pG, pWh1Thi, pWh1Tlo,
                                              /*rA=*/1, /*rB=*/TT,
                                              /*gen_base=*/(unsigned)TT);

    // 6) Wd^T split; logits = H1 @ Wd + bd -> d_out, with fused softmax partials
    transpose_split_kernel<<<dim3(NPADV / 32, 16), tsblk>>>(Wd, VV, pWThi, pWTlo);
    gemm_mma<<<dim3(NPADV / 128, MROWS / 128), 256, GEMM_SMEM>>>(pAhi, pAlo, bd, out, VV, 1);

    // 7) final per-row NLL from partials
    softmax_final_kernel<<<MROWS / 8, 256>>>(out, labels);

    // 8) perplexity scalar
    perplexity_kernel<<<1, 256>>>(out, (long long)out_size);
}